// round 14
// baseline (speedup 1.0000x reference)
#include <cuda_runtime.h>
#include <cuda_fp16.h>
#include <math.h>
#include <stdint.h>

// ---------------------------------------------------------------------------
// Problem constants
// ---------------------------------------------------------------------------
#define B_    2
#define S_    2048
#define D_    1024
#define H_    16
#define DH_   64
#define M_TOT (B_ * S_)      // 4096
#define QKV_N (3 * D_)       // 3072
#define K_    1024
#define SCALE 0.125f
#define LOG2E 1.4426950408889634f

// ---------------------------------------------------------------------------
// Scratch: single fp16 (q pre-scaled by SCALE*log2(e) in GEMM1 epilogue)
// ---------------------------------------------------------------------------
__device__ __half g_xh[M_TOT * D_];
__device__ __half g_wqh[QKV_N * D_];
__device__ __half g_woh[D_ * D_];
__device__ __half g_qkv[M_TOT * QKV_N];
__device__ __half g_att[M_TOT * D_];

// ---------------------------------------------------------------------------
// Helpers
// ---------------------------------------------------------------------------
__device__ __forceinline__ uint32_t sptr(const void* p) {
    return (uint32_t)__cvta_generic_to_shared(p);
}
__device__ __forceinline__ void cp16(uint32_t d, const void* s) {
    asm volatile("cp.async.cg.shared.global [%0], [%1], 16;" :: "r"(d), "l"(s));
}
#define CP_COMMIT() asm volatile("cp.async.commit_group;" ::: "memory")
#define CP_WAIT(n)  asm volatile("cp.async.wait_group %0;" :: "n"(n) : "memory")

__device__ __forceinline__ uint32_t sw128(uint32_t o) {   // Swizzle<3,4,3>
    return o ^ ((o >> 3) & 0x70);
}
__device__ __forceinline__ void ldsm4(uint32_t a, uint32_t r[4]) {
    asm volatile("ldmatrix.sync.aligned.m8n8.x4.shared.b16 {%0,%1,%2,%3}, [%4];"
                 : "=r"(r[0]), "=r"(r[1]), "=r"(r[2]), "=r"(r[3]) : "r"(a));
}
__device__ __forceinline__ void ldsm4t(uint32_t a, uint32_t r[4]) {
    asm volatile("ldmatrix.sync.aligned.m8n8.x4.trans.shared.b16 {%0,%1,%2,%3}, [%4];"
                 : "=r"(r[0]), "=r"(r[1]), "=r"(r[2]), "=r"(r[3]) : "r"(a));
}
__device__ __forceinline__ void mma_f16(float c[4], const uint32_t a[4],
                                        uint32_t b0, uint32_t b1) {
    asm volatile(
        "mma.sync.aligned.m16n8k16.row.col.f32.f16.f16.f32 "
        "{%0,%1,%2,%3}, {%4,%5,%6,%7}, {%8,%9}, {%0,%1,%2,%3};"
        : "+f"(c[0]), "+f"(c[1]), "+f"(c[2]), "+f"(c[3])
        : "r"(a[0]), "r"(a[1]), "r"(a[2]), "r"(a[3]), "r"(b0), "r"(b1));
}
__device__ __forceinline__ uint32_t pack_h2(float a, float b) {
    __half2 hp = __floats2half2_rn(a, b);
    return *(uint32_t*)&hp;
}

// ---------------------------------------------------------------------------
// Convert: fp32 -> fp16
// ---------------------------------------------------------------------------
__global__ void conv_f16(const float* __restrict__ src, __half* __restrict__ dst, int n)
{
    int i = (blockIdx.x * blockDim.x + threadIdx.x) * 4;
    for (; i < n; i += gridDim.x * blockDim.x * 4) {
        float4 v = *(const float4*)(src + i);
        __half2 a = __floats2half2_rn(v.x, v.y);
        __half2 b = __floats2half2_rn(v.z, v.w);
        uint2 o = { *(uint32_t*)&a, *(uint32_t*)&b };
        *(uint2*)(dst + i) = o;
    }
}

// ---------------------------------------------------------------------------
// GEMM: C[M,N] = A[M,1024] @ B[N,1024]^T, single-pass fp16, f32 accum.
// CTA 128x256, 8 warps (2x4, warp tile 64x64), BK=64 (128 mma/warp/barrier),
// 3-stage cp.async, SW128 smem layout.  (unchanged from R13 except QSCALE
// now multiplies q columns by SCALE*log2e for exp2-domain softmax)
// ---------------------------------------------------------------------------
#define GA 16384
#define GB 32768
#define GST (GA + GB)                   // 49152
#define GEMM_SMEM (3 * GST)             // 147456
#define NCH 16

template<bool HOUT, bool QSCALE>
__global__ __launch_bounds__(256) void gemm_mma(
    const __half* __restrict__ As, const __half* __restrict__ Bs,
    float* __restrict__ Cf, __half* __restrict__ Ch, int N)
{
    extern __shared__ char smx[];
    const int tid = threadIdx.x, lane = tid & 31, wid = tid >> 5;
    const int bm = blockIdx.y * 128, bn = blockIdx.x * 256;
    const int m0 = (wid >> 2) * 64, n0 = (wid & 3) * 64;

    const __half* pA = As + (size_t)bm * K_;
    const __half* pB = Bs + (size_t)bn * K_;

    float acc[4][8][4];
    #pragma unroll
    for (int i = 0; i < 4; i++)
        #pragma unroll
        for (int j = 0; j < 8; j++)
            #pragma unroll
            for (int q = 0; q < 4; q++) acc[i][j][q] = 0.0f;

    auto load_stage = [&](int s, int k0) {
        char* base = smx + s * GST;
        #pragma unroll
        for (int i = 0; i < 4; i++) {
            int idx = tid + i * 256;
            int r = idx >> 3, c = idx & 7;
            cp16(sptr(base) + sw128((uint32_t)(r * 128 + c * 16)),
                 pA + (size_t)r * K_ + k0 + c * 8);
        }
        #pragma unroll
        for (int i = 0; i < 8; i++) {
            int idx = tid + i * 256;
            int r = idx >> 3, c = idx & 7;
            cp16(sptr(base + GA) + sw128((uint32_t)(r * 128 + c * 16)),
                 pB + (size_t)r * K_ + k0 + c * 8);
        }
    };

    load_stage(0, 0);   CP_COMMIT();
    load_stage(1, 64);  CP_COMMIT();

    const int row_in = lane & 7, g = lane >> 3;

    for (int kc = 0; kc < NCH; kc++) {
        if (kc == NCH - 1) { CP_WAIT(0); } else { CP_WAIT(1); }
        __syncthreads();
        if (kc + 2 < NCH) {
            load_stage((kc + 2) % 3, (kc + 2) * 64);
            CP_COMMIT();
        }

        char* base = smx + (kc % 3) * GST;
        uint32_t bA = sptr(base), bB = bA + GA;

        #pragma unroll
        for (int ks = 0; ks < 4; ks++) {
            uint32_t af[4][4];
            #pragma unroll
            for (int mt = 0; mt < 4; mt++) {
                uint32_t off = sw128((uint32_t)(m0 + mt * 16 + row_in + (g & 1) * 8) * 128
                                     + (ks * 16 + (g >> 1) * 8) * 2);
                ldsm4(bA + off, af[mt]);
            }
            #pragma unroll
            for (int gb = 0; gb < 4; gb++) {
                uint32_t bf[4];
                uint32_t off = sw128((uint32_t)(n0 + gb * 16 + ((g >> 1) & 1) * 8 + row_in) * 128
                                     + (ks * 16 + (g & 1) * 8) * 2);
                ldsm4(bB + off, bf);
                #pragma unroll
                for (int mt = 0; mt < 4; mt++)
                    #pragma unroll
                    for (int hf = 0; hf < 2; hf++) {
                        int nt = gb * 2 + hf, ix = hf * 2;
                        mma_f16(acc[mt][nt], af[mt], bf[ix], bf[ix + 1]);
                    }
            }
        }
    }

    #pragma unroll
    for (int mt = 0; mt < 4; mt++)
        #pragma unroll
        for (int nt = 0; nt < 8; nt++) {
            int row = bm + m0 + mt * 16 + (lane >> 2);
            int col = bn + n0 + nt * 8 + (lane & 3) * 2;
            float* c = acc[mt][nt];
            float sc = (QSCALE && col < D_) ? (SCALE * LOG2E) : 1.0f;
            if (HOUT) {
                *(uint32_t*)(Ch + (size_t)row * N + col) = pack_h2(c[0] * sc, c[1] * sc);
                *(uint32_t*)(Ch + (size_t)(row + 8) * N + col) = pack_h2(c[2] * sc, c[3] * sc);
            } else {
                *(float2*)(Cf + (size_t)row * N + col) = make_float2(c[0], c[1]);
                *(float2*)(Cf + (size_t)(row + 8) * N + col) = make_float2(c[2], c[3]);
            }
        }
}

// ---------------------------------------------------------------------------
// Flash attention: 4 warps x 32 q-rows, single-pass fp16, log2-domain
// softmax (Q pre-scaled by SCALE*log2e; exp2f only). 3-stage KV pipeline,
// ONE __syncthreads per key-tile. smem 64 KB -> 2 CTAs/SM.
// ---------------------------------------------------------------------------
#define SQ   0
#define SKV0 16384
#define KVSTAGE 16384            // K 8192 | V 8192
#define ATT_SMEM (SKV0 + 3 * KVSTAGE)   // 65536
#define NT (S_ / 64)             // 32

__global__ __launch_bounds__(128, 2) void attn_mma()
{
    extern __shared__ char smx[];
    const int tid = threadIdx.x, lane = tid & 31, warp = tid >> 5;
    const int qt = blockIdx.x;
    const int b  = blockIdx.y >> 4;
    const int h  = blockIdx.y & 15;
    const int qrow0 = b * S_ + qt * 128;

    const __half* qp = g_qkv + (size_t)qrow0 * QKV_N + h * DH_;
    const __half* kp = g_qkv + (size_t)(b * S_) * QKV_N + D_ + h * DH_;
    const __half* vp = g_qkv + (size_t)(b * S_) * QKV_N + 2 * D_ + h * DH_;

    uint32_t sb = sptr(smx);

    // Q tile: 128 rows x 128B, SW128
    #pragma unroll
    for (int i = 0; i < 8; i++) {
        int idx = tid + i * 128;
        int r = idx >> 3, c = idx & 7;
        cp16(sb + SQ + sw128((uint32_t)(r * 128 + c * 16)), qp + (size_t)r * QKV_N + c * 8);
    }
    CP_COMMIT();

    auto ld_kv = [&](int s, int krow) {
        uint32_t base = sb + SKV0 + s * KVSTAGE;
        #pragma unroll
        for (int i = 0; i < 4; i++) {
            int idx = tid + i * 128;
            int r = idx >> 3, c = idx & 7;
            size_t go = (size_t)(krow + r) * QKV_N + c * 8;
            uint32_t so = sw128((uint32_t)(r * 128 + c * 16));
            cp16(base + so,        kp + go);
            cp16(base + 8192 + so, vp + go);
        }
    };

    ld_kv(0, 0);   CP_COMMIT();
    ld_kv(1, 64);  CP_COMMIT();
    CP_WAIT(2);                         // Q group complete
    __syncthreads();

    const int row_in = lane & 7, g = lane >> 3;

    uint32_t qa[2][4][4];
    #pragma unroll
    for (int mt = 0; mt < 2; mt++)
        #pragma unroll
        for (int ks = 0; ks < 4; ks++) {
            uint32_t off = sw128((uint32_t)(warp * 32 + mt * 16 + row_in + (g & 1) * 8) * 128
                                 + (ks * 16 + (g >> 1) * 8) * 2);
            ldsm4(sb + SQ + off, qa[mt][ks]);
        }

    float m[4] = {-1e30f, -1e30f, -1e30f, -1e30f};
    float l[4] = {0.0f, 0.0f, 0.0f, 0.0f};
    float O[2][8][4];
    #pragma unroll
    for (int mt = 0; mt < 2; mt++)
        #pragma unroll
        for (int nt = 0; nt < 8; nt++)
            #pragma unroll
            for (int q = 0; q < 4; q++) O[mt][nt][q] = 0.0f;

    for (int kt = 0; kt < NT; kt++) {
        if (kt == NT - 1) { CP_WAIT(0); } else { CP_WAIT(1); }
        __syncthreads();                 // single barrier per key-tile
        if (kt + 2 < NT) {
            ld_kv((kt + 2) % 3, (kt + 2) * 64);
            CP_COMMIT();
        }

        uint32_t kvb = sb + SKV0 + (kt % 3) * KVSTAGE;

        // ---- S = Q @ K^T (log2-domain: scale*log2e folded into Q) ----
        float s[2][8][4];
        #pragma unroll
        for (int mt = 0; mt < 2; mt++)
            #pragma unroll
            for (int nt = 0; nt < 8; nt++)
                #pragma unroll
                for (int q = 0; q < 4; q++) s[mt][nt][q] = 0.0f;

        #pragma unroll
        for (int ks = 0; ks < 4; ks++) {
            #pragma unroll
            for (int gb = 0; gb < 4; gb++) {
                uint32_t bf[4];
                uint32_t off = sw128((uint32_t)(gb * 16 + ((g >> 1) & 1) * 8 + row_in) * 128
                                     + (ks * 16 + (g & 1) * 8) * 2);
                ldsm4(kvb + off, bf);
                #pragma unroll
                for (int mt = 0; mt < 2; mt++)
                    #pragma unroll
                    for (int hf = 0; hf < 2; hf++) {
                        int nt = gb * 2 + hf, ix = hf * 2;
                        mma_f16(s[mt][nt], qa[mt][ks], bf[ix], bf[ix + 1]);
                    }
            }
        }

        // ---- online softmax in log2 domain (exp2 only) ----
        #pragma unroll
        for (int mt = 0; mt < 2; mt++) {
            float mx0 = -1e30f, mx1 = -1e30f;
            #pragma unroll
            for (int nt = 0; nt < 8; nt++) {
                mx0 = fmaxf(mx0, fmaxf(s[mt][nt][0], s[mt][nt][1]));
                mx1 = fmaxf(mx1, fmaxf(s[mt][nt][2], s[mt][nt][3]));
            }
            mx0 = fmaxf(mx0, __shfl_xor_sync(0xffffffffu, mx0, 1));
            mx0 = fmaxf(mx0, __shfl_xor_sync(0xffffffffu, mx0, 2));
            mx1 = fmaxf(mx1, __shfl_xor_sync(0xffffffffu, mx1, 1));
            mx1 = fmaxf(mx1, __shfl_xor_sync(0xffffffffu, mx1, 2));

            float mn0 = fmaxf(m[2 * mt], mx0), mn1 = fmaxf(m[2 * mt + 1], mx1);
            if (mn0 > m[2 * mt] || mn1 > m[2 * mt + 1]) {
                float c0 = exp2f(m[2 * mt] - mn0), c1 = exp2f(m[2 * mt + 1] - mn1);
                l[2 * mt] *= c0; l[2 * mt + 1] *= c1;
                #pragma unroll
                for (int nt = 0; nt < 8; nt++) {
                    O[mt][nt][0] *= c0; O[mt][nt][1] *= c0;
                    O[mt][nt][2] *= c1; O[mt][nt][3] *= c1;
                }
                m[2 * mt] = mn0; m[2 * mt + 1] = mn1;
            }
            float sum0 = 0.0f, sum1 = 0.0f;
            #pragma unroll
            for (int nt = 0; nt < 8; nt++) {
                s[mt][nt][0] = exp2f(s[mt][nt][0] - m[2 * mt]);     sum0 += s[mt][nt][0];
                s[mt][nt][1] = exp2f(s[mt][nt][1] - m[2 * mt]);     sum0 += s[mt][nt][1];
                s[mt][nt][2] = exp2f(s[mt][nt][2] - m[2 * mt + 1]); sum1 += s[mt][nt][2];
                s[mt][nt][3] = exp2f(s[mt][nt][3] - m[2 * mt + 1]); sum1 += s[mt][nt][3];
            }
            sum0 += __shfl_xor_sync(0xffffffffu, sum0, 1);
            sum0 += __shfl_xor_sync(0xffffffffu, sum0, 2);
            sum1 += __shfl_xor_sync(0xffffffffu, sum1, 1);
            sum1 += __shfl_xor_sync(0xffffffffu, sum1, 2);
            l[2 * mt] += sum0;
            l[2 * mt + 1] += sum1;
        }

        // ---- O += P @ V ----
        #pragma unroll
        for (int j = 0; j < 4; j++) {
            uint32_t pa[2][4];
            #pragma unroll
            for (int mt = 0; mt < 2; mt++) {
                pa[mt][0] = pack_h2(s[mt][2 * j][0],     s[mt][2 * j][1]);
                pa[mt][1] = pack_h2(s[mt][2 * j][2],     s[mt][2 * j][3]);
                pa[mt][2] = pack_h2(s[mt][2 * j + 1][0], s[mt][2 * j + 1][1]);
                pa[mt][3] = pack_h2(s[mt][2 * j + 1][2], s[mt][2 * j + 1][3]);
            }
            #pragma unroll
            for (int gv = 0; gv < 4; gv++) {
                uint32_t vf[4];
                uint32_t off = sw128((uint32_t)(j * 16 + (g & 1) * 8 + row_in) * 128
                                     + (gv * 16 + (g >> 1) * 8) * 2);
                ldsm4t(kvb + 8192 + off, vf);
                #pragma unroll
                for (int mt = 0; mt < 2; mt++)
                    #pragma unroll
                    for (int hf = 0; hf < 2; hf++) {
                        int nt = gv * 2 + hf, ix = hf * 2;
                        mma_f16(O[mt][nt], pa[mt], vf[ix], vf[ix + 1]);
                    }
            }
        }
    }

    // ---- epilogue: normalize, write fp16 ----
    #pragma unroll
    for (int mt = 0; mt < 2; mt++) {
        float inv0 = 1.0f / (l[2 * mt] + 1e-6f);
        float inv1 = 1.0f / (l[2 * mt + 1] + 1e-6f);
        int r0g = qrow0 + warp * 32 + mt * 16 + (lane >> 2);
        #pragma unroll
        for (int nt = 0; nt < 8; nt++) {
            int col = h * DH_ + nt * 8 + (lane & 3) * 2;
            *(uint32_t*)(g_att + (size_t)r0g * D_ + col) =
                pack_h2(O[mt][nt][0] * inv0, O[mt][nt][1] * inv0);
            *(uint32_t*)(g_att + (size_t)(r0g + 8) * D_ + col) =
                pack_h2(O[mt][nt][2] * inv1, O[mt][nt][3] * inv1);
        }
    }
}

// ---------------------------------------------------------------------------
// Launch
// ---------------------------------------------------------------------------
extern "C" void kernel_launch(void* const* d_in, const int* in_sizes, int n_in,
                              void* d_out, int out_size)
{
    const float* x    = (const float*)d_in[0];
    const float* Wqkv = (const float*)d_in[1];
    const float* Wout = (const float*)d_in[2];
    float* out = (float*)d_out;

    __half *xh, *wqh, *woh, *qkv, *att;
    cudaGetSymbolAddress((void**)&xh,  g_xh);
    cudaGetSymbolAddress((void**)&wqh, g_wqh);
    cudaGetSymbolAddress((void**)&woh, g_woh);
    cudaGetSymbolAddress((void**)&qkv, g_qkv);
    cudaGetSymbolAddress((void**)&att, g_att);

    cudaFuncSetAttribute((const void*)gemm_mma<true, true>,
                         cudaFuncAttributeMaxDynamicSharedMemorySize, GEMM_SMEM);
    cudaFuncSetAttribute((const void*)gemm_mma<false, false>,
                         cudaFuncAttributeMaxDynamicSharedMemorySize, GEMM_SMEM);
    cudaFuncSetAttribute(attn_mma,
                         cudaFuncAttributeMaxDynamicSharedMemorySize, ATT_SMEM);

    // 0) convert inputs to fp16
    conv_f16<<<512, 256>>>(x,    xh,  M_TOT * D_);
    conv_f16<<<512, 256>>>(Wqkv, wqh, QKV_N * D_);
    conv_f16<<<256, 256>>>(Wout, woh, D_ * D_);

    // 1) qkv = x @ Wqkv^T -> fp16 (q columns pre-scaled by SCALE*log2e)
    gemm_mma<true, true><<<dim3(QKV_N / 256, M_TOT / 128), 256, GEMM_SMEM>>>(
        xh, wqh, nullptr, qkv, QKV_N);

    // 2) attention -> g_att (fp16)
    attn_mma<<<dim3(S_ / 128, B_ * H_), 128, ATT_SMEM>>>();

    // 3) out = attn @ Wout^T -> fp32
    gemm_mma<false, false><<<dim3(D_ / 256, M_TOT / 128), 256, GEMM_SMEM>>>(
        att, woh, out, nullptr, D_);
}

// round 15
// speedup vs baseline: 1.0372x; 1.0372x over previous
#include <cuda_runtime.h>
#include <cuda_fp16.h>
#include <math.h>
#include <stdint.h>

// ---------------------------------------------------------------------------
// Problem constants
// ---------------------------------------------------------------------------
#define B_    2
#define S_    2048
#define D_    1024
#define H_    16
#define DH_   64
#define M_TOT (B_ * S_)      // 4096
#define QKV_N (3 * D_)       // 3072
#define K_    1024
#define SCALE 0.125f
#define LOG2E 1.4426950408889634f

// ---------------------------------------------------------------------------
// Scratch: single fp16 (q pre-scaled by SCALE*log2(e) in GEMM1 epilogue)
// ---------------------------------------------------------------------------
__device__ __half g_xh[M_TOT * D_];
__device__ __half g_wqh[QKV_N * D_];
__device__ __half g_woh[D_ * D_];
__device__ __half g_qkv[M_TOT * QKV_N];
__device__ __half g_att[M_TOT * D_];

// ---------------------------------------------------------------------------
// Helpers
// ---------------------------------------------------------------------------
__device__ __forceinline__ uint32_t sptr(const void* p) {
    return (uint32_t)__cvta_generic_to_shared(p);
}
__device__ __forceinline__ void cp16(uint32_t d, const void* s) {
    asm volatile("cp.async.cg.shared.global [%0], [%1], 16;" :: "r"(d), "l"(s));
}
#define CP_COMMIT() asm volatile("cp.async.commit_group;" ::: "memory")
#define CP_WAIT(n)  asm volatile("cp.async.wait_group %0;" :: "n"(n) : "memory")

__device__ __forceinline__ uint32_t sw128(uint32_t o) {   // Swizzle<3,4,3>
    return o ^ ((o >> 3) & 0x70);
}
__device__ __forceinline__ void ldsm4(uint32_t a, uint32_t r[4]) {
    asm volatile("ldmatrix.sync.aligned.m8n8.x4.shared.b16 {%0,%1,%2,%3}, [%4];"
                 : "=r"(r[0]), "=r"(r[1]), "=r"(r[2]), "=r"(r[3]) : "r"(a));
}
__device__ __forceinline__ void ldsm4t(uint32_t a, uint32_t r[4]) {
    asm volatile("ldmatrix.sync.aligned.m8n8.x4.trans.shared.b16 {%0,%1,%2,%3}, [%4];"
                 : "=r"(r[0]), "=r"(r[1]), "=r"(r[2]), "=r"(r[3]) : "r"(a));
}
__device__ __forceinline__ void mma_f16(float c[4], const uint32_t a[4],
                                        uint32_t b0, uint32_t b1) {
    asm volatile(
        "mma.sync.aligned.m16n8k16.row.col.f32.f16.f16.f32 "
        "{%0,%1,%2,%3}, {%4,%5,%6,%7}, {%8,%9}, {%0,%1,%2,%3};"
        : "+f"(c[0]), "+f"(c[1]), "+f"(c[2]), "+f"(c[3])
        : "r"(a[0]), "r"(a[1]), "r"(a[2]), "r"(a[3]), "r"(b0), "r"(b1));
}
__device__ __forceinline__ uint32_t pack_h2(float a, float b) {
    __half2 hp = __floats2half2_rn(a, b);
    return *(uint32_t*)&hp;
}
// one MUFU op computing exp2 of two fp16 values
__device__ __forceinline__ uint32_t ex2h2(uint32_t x) {
    uint32_t r;
    asm("ex2.approx.f16x2 %0, %1;" : "=r"(r) : "r"(x));
    return r;
}
__device__ __forceinline__ float2 h2f2(uint32_t x) {
    return __half22float2(*(__half2*)&x);
}

// ---------------------------------------------------------------------------
// Convert: fp32 -> fp16
// ---------------------------------------------------------------------------
__global__ void conv_f16(const float* __restrict__ src, __half* __restrict__ dst, int n)
{
    int i = (blockIdx.x * blockDim.x + threadIdx.x) * 4;
    for (; i < n; i += gridDim.x * blockDim.x * 4) {
        float4 v = *(const float4*)(src + i);
        __half2 a = __floats2half2_rn(v.x, v.y);
        __half2 b = __floats2half2_rn(v.z, v.w);
        uint2 o = { *(uint32_t*)&a, *(uint32_t*)&b };
        *(uint2*)(dst + i) = o;
    }
}

// ---------------------------------------------------------------------------
// GEMM: C[M,N] = A[M,1024] @ B[N,1024]^T, single-pass fp16, f32 accum.
// CTA 128x256, 8 warps (2x4, warp tile 64x64), BK=64, 3-stage cp.async,
// SW128 smem. QSCALE folds SCALE*log2e into q columns.  (R13-proven, 85us)
// ---------------------------------------------------------------------------
#define GA 16384
#define GB 32768
#define GST (GA + GB)                   // 49152
#define GEMM_SMEM (3 * GST)             // 147456
#define NCH 16

template<bool HOUT, bool QSCALE>
__global__ __launch_bounds__(256) void gemm_mma(
    const __half* __restrict__ As, const __half* __restrict__ Bs,
    float* __restrict__ Cf, __half* __restrict__ Ch, int N)
{
    extern __shared__ char smx[];
    const int tid = threadIdx.x, lane = tid & 31, wid = tid >> 5;
    const int bm = blockIdx.y * 128, bn = blockIdx.x * 256;
    const int m0 = (wid >> 2) * 64, n0 = (wid & 3) * 64;

    const __half* pA = As + (size_t)bm * K_;
    const __half* pB = Bs + (size_t)bn * K_;

    float acc[4][8][4];
    #pragma unroll
    for (int i = 0; i < 4; i++)
        #pragma unroll
        for (int j = 0; j < 8; j++)
            #pragma unroll
            for (int q = 0; q < 4; q++) acc[i][j][q] = 0.0f;

    auto load_stage = [&](int s, int k0) {
        char* base = smx + s * GST;
        #pragma unroll
        for (int i = 0; i < 4; i++) {
            int idx = tid + i * 256;
            int r = idx >> 3, c = idx & 7;
            cp16(sptr(base) + sw128((uint32_t)(r * 128 + c * 16)),
                 pA + (size_t)r * K_ + k0 + c * 8);
        }
        #pragma unroll
        for (int i = 0; i < 8; i++) {
            int idx = tid + i * 256;
            int r = idx >> 3, c = idx & 7;
            cp16(sptr(base + GA) + sw128((uint32_t)(r * 128 + c * 16)),
                 pB + (size_t)r * K_ + k0 + c * 8);
        }
    };

    load_stage(0, 0);   CP_COMMIT();
    load_stage(1, 64);  CP_COMMIT();

    const int row_in = lane & 7, g = lane >> 3;

    for (int kc = 0; kc < NCH; kc++) {
        if (kc == NCH - 1) { CP_WAIT(0); } else { CP_WAIT(1); }
        __syncthreads();
        if (kc + 2 < NCH) {
            load_stage((kc + 2) % 3, (kc + 2) * 64);
            CP_COMMIT();
        }

        char* base = smx + (kc % 3) * GST;
        uint32_t bA = sptr(base), bB = bA + GA;

        #pragma unroll
        for (int ks = 0; ks < 4; ks++) {
            uint32_t af[4][4];
            #pragma unroll
            for (int mt = 0; mt < 4; mt++) {
                uint32_t off = sw128((uint32_t)(m0 + mt * 16 + row_in + (g & 1) * 8) * 128
                                     + (ks * 16 + (g >> 1) * 8) * 2);
                ldsm4(bA + off, af[mt]);
            }
            #pragma unroll
            for (int gb = 0; gb < 4; gb++) {
                uint32_t bf[4];
                uint32_t off = sw128((uint32_t)(n0 + gb * 16 + ((g >> 1) & 1) * 8 + row_in) * 128
                                     + (ks * 16 + (g & 1) * 8) * 2);
                ldsm4(bB + off, bf);
                #pragma unroll
                for (int mt = 0; mt < 4; mt++)
                    #pragma unroll
                    for (int hf = 0; hf < 2; hf++) {
                        int nt = gb * 2 + hf, ix = hf * 2;
                        mma_f16(acc[mt][nt], af[mt], bf[ix], bf[ix + 1]);
                    }
            }
        }
    }

    #pragma unroll
    for (int mt = 0; mt < 4; mt++)
        #pragma unroll
        for (int nt = 0; nt < 8; nt++) {
            int row = bm + m0 + mt * 16 + (lane >> 2);
            int col = bn + n0 + nt * 8 + (lane & 3) * 2;
            float* c = acc[mt][nt];
            float sc = (QSCALE && col < D_) ? (SCALE * LOG2E) : 1.0f;
            if (HOUT) {
                *(uint32_t*)(Ch + (size_t)row * N + col) = pack_h2(c[0] * sc, c[1] * sc);
                *(uint32_t*)(Ch + (size_t)(row + 8) * N + col) = pack_h2(c[2] * sc, c[3] * sc);
            } else {
                *(float2*)(Cf + (size_t)row * N + col) = make_float2(c[0], c[1]);
                *(float2*)(Cf + (size_t)(row + 8) * N + col) = make_float2(c[2], c[3]);
            }
        }
}

// ---------------------------------------------------------------------------
// Flash attention: 4 warps x 32 q-rows, single-pass fp16, log2-domain
// softmax with ex2.approx.f16x2 (one MUFU per 2 elements; output is the PV
// operand directly). R13 structure: 2-stage KV double-buffer, smem 48 KB,
// 128 threads, 2 CTAs/SM.
// ---------------------------------------------------------------------------
#define SQ   0
#define SKV0 16384
#define KVSTAGE 16384            // K 8192 | V 8192
#define ATT_SMEM (SKV0 + 2 * KVSTAGE)   // 49152
#define NT (S_ / 64)             // 32

__global__ __launch_bounds__(128, 2) void attn_mma()
{
    extern __shared__ char smx[];
    const int tid = threadIdx.x, lane = tid & 31, warp = tid >> 5;
    const int qt = blockIdx.x;
    const int b  = blockIdx.y >> 4;
    const int h  = blockIdx.y & 15;
    const int qrow0 = b * S_ + qt * 128;

    const __half* qp = g_qkv + (size_t)qrow0 * QKV_N + h * DH_;
    const __half* kp = g_qkv + (size_t)(b * S_) * QKV_N + D_ + h * DH_;
    const __half* vp = g_qkv + (size_t)(b * S_) * QKV_N + 2 * D_ + h * DH_;

    uint32_t sb = sptr(smx);

    // Q tile: 128 rows x 128B, SW128
    #pragma unroll
    for (int i = 0; i < 8; i++) {
        int idx = tid + i * 128;
        int r = idx >> 3, c = idx & 7;
        cp16(sb + SQ + sw128((uint32_t)(r * 128 + c * 16)), qp + (size_t)r * QKV_N + c * 8);
    }
    CP_COMMIT();

    auto ld_kv = [&](int s, int krow) {
        uint32_t base = sb + SKV0 + s * KVSTAGE;
        #pragma unroll
        for (int i = 0; i < 4; i++) {
            int idx = tid + i * 128;
            int r = idx >> 3, c = idx & 7;
            size_t go = (size_t)(krow + r) * QKV_N + c * 8;
            uint32_t so = sw128((uint32_t)(r * 128 + c * 16));
            cp16(base + so,        kp + go);
            cp16(base + 8192 + so, vp + go);
        }
    };

    ld_kv(0, 0);
    CP_COMMIT();
    CP_WAIT(1);
    __syncthreads();

    const int row_in = lane & 7, g = lane >> 3;

    uint32_t qa[2][4][4];
    #pragma unroll
    for (int mt = 0; mt < 2; mt++)
        #pragma unroll
        for (int ks = 0; ks < 4; ks++) {
            uint32_t off = sw128((uint32_t)(warp * 32 + mt * 16 + row_in + (g & 1) * 8) * 128
                                 + (ks * 16 + (g >> 1) * 8) * 2);
            ldsm4(sb + SQ + off, qa[mt][ks]);
        }

    float m[4] = {-1e30f, -1e30f, -1e30f, -1e30f};
    float l[4] = {0.0f, 0.0f, 0.0f, 0.0f};
    float O[2][8][4];
    #pragma unroll
    for (int mt = 0; mt < 2; mt++)
        #pragma unroll
        for (int nt = 0; nt < 8; nt++)
            #pragma unroll
            for (int q = 0; q < 4; q++) O[mt][nt][q] = 0.0f;

    for (int kt = 0; kt < NT; kt++) {
        if (kt + 1 < NT) {
            ld_kv((kt + 1) & 1, (kt + 1) * 64);
            CP_COMMIT();
            CP_WAIT(1);
        } else {
            CP_WAIT(0);
        }
        __syncthreads();

        uint32_t kvb = sb + SKV0 + (kt & 1) * KVSTAGE;

        // ---- S = Q @ K^T (log2-domain: SCALE*log2e folded into Q) ----
        float s[2][8][4];
        #pragma unroll
        for (int mt = 0; mt < 2; mt++)
            #pragma unroll
            for (int nt = 0; nt < 8; nt++)
                #pragma unroll
                for (int q = 0; q < 4; q++) s[mt][nt][q] = 0.0f;

        #pragma unroll
        for (int ks = 0; ks < 4; ks++) {
            #pragma unroll
            for (int gb = 0; gb < 4; gb++) {
                uint32_t bf[4];
                uint32_t off = sw128((uint32_t)(gb * 16 + ((g >> 1) & 1) * 8 + row_in) * 128
                                     + (ks * 16 + (g & 1) * 8) * 2);
                ldsm4(kvb + off, bf);
                #pragma unroll
                for (int mt = 0; mt < 2; mt++)
                    #pragma unroll
                    for (int hf = 0; hf < 2; hf++) {
                        int nt = gb * 2 + hf, ix = hf * 2;
                        mma_f16(s[mt][nt], qa[mt][ks], bf[ix], bf[ix + 1]);
                    }
            }
        }

        // ---- online softmax: P = exp2(s - m) via ex2.approx.f16x2 ----
        uint32_t ph[2][8][2];   // fp16x2 P values, directly the PV operands
        #pragma unroll
        for (int mt = 0; mt < 2; mt++) {
            float mx0 = -1e30f, mx1 = -1e30f;
            #pragma unroll
            for (int nt = 0; nt < 8; nt++) {
                mx0 = fmaxf(mx0, fmaxf(s[mt][nt][0], s[mt][nt][1]));
                mx1 = fmaxf(mx1, fmaxf(s[mt][nt][2], s[mt][nt][3]));
            }
            mx0 = fmaxf(mx0, __shfl_xor_sync(0xffffffffu, mx0, 1));
            mx0 = fmaxf(mx0, __shfl_xor_sync(0xffffffffu, mx0, 2));
            mx1 = fmaxf(mx1, __shfl_xor_sync(0xffffffffu, mx1, 1));
            mx1 = fmaxf(mx1, __shfl_xor_sync(0xffffffffu, mx1, 2));

            float mn0 = fmaxf(m[2 * mt], mx0), mn1 = fmaxf(m[2 * mt + 1], mx1);
            if (mn0 > m[2 * mt] || mn1 > m[2 * mt + 1]) {
                float c0 = exp2f(m[2 * mt] - mn0), c1 = exp2f(m[2 * mt + 1] - mn1);
                l[2 * mt] *= c0; l[2 * mt + 1] *= c1;
                #pragma unroll
                for (int nt = 0; nt < 8; nt++) {
                    O[mt][nt][0] *= c0; O[mt][nt][1] *= c0;
                    O[mt][nt][2] *= c1; O[mt][nt][3] *= c1;
                }
                m[2 * mt] = mn0; m[2 * mt + 1] = mn1;
            }
            float m0v = m[2 * mt], m1v = m[2 * mt + 1];
            float sum0 = 0.0f, sum1 = 0.0f;
            #pragma unroll
            for (int nt = 0; nt < 8; nt++) {
                uint32_t p01 = ex2h2(pack_h2(s[mt][nt][0] - m0v, s[mt][nt][1] - m0v));
                uint32_t p23 = ex2h2(pack_h2(s[mt][nt][2] - m1v, s[mt][nt][3] - m1v));
                ph[mt][nt][0] = p01;
                ph[mt][nt][1] = p23;
                float2 f0 = h2f2(p01);
                float2 f1 = h2f2(p23);
                sum0 += f0.x + f0.y;
                sum1 += f1.x + f1.y;
            }
            sum0 += __shfl_xor_sync(0xffffffffu, sum0, 1);
            sum0 += __shfl_xor_sync(0xffffffffu, sum0, 2);
            sum1 += __shfl_xor_sync(0xffffffffu, sum1, 1);
            sum1 += __shfl_xor_sync(0xffffffffu, sum1, 2);
            l[2 * mt] += sum0;
            l[2 * mt + 1] += sum1;
        }

        // ---- O += P @ V (P fragments already in fp16x2) ----
        #pragma unroll
        for (int j = 0; j < 4; j++) {
            #pragma unroll
            for (int gv = 0; gv < 4; gv++) {
                uint32_t vf[4];
                uint32_t off = sw128((uint32_t)(j * 16 + (g & 1) * 8 + row_in) * 128
                                     + (gv * 16 + (g >> 1) * 8) * 2);
                ldsm4t(kvb + 8192 + off, vf);
                #pragma unroll
                for (int mt = 0; mt < 2; mt++) {
                    uint32_t pa[4] = { ph[mt][2 * j][0],     ph[mt][2 * j][1],
                                       ph[mt][2 * j + 1][0], ph[mt][2 * j + 1][1] };
                    #pragma unroll
                    for (int hf = 0; hf < 2; hf++) {
                        int nt = gv * 2 + hf, ix = hf * 2;
                        mma_f16(O[mt][nt], pa, vf[ix], vf[ix + 1]);
                    }
                }
            }
        }
        __syncthreads();
    }

    // ---- epilogue: normalize, write fp16 ----
    #pragma unroll
    for (int mt = 0; mt < 2; mt++) {
        float inv0 = 1.0f / (l[2 * mt] + 1e-6f);
        float inv1 = 1.0f / (l[2 * mt + 1] + 1e-6f);
        int r0g = qrow0 + warp * 32 + mt * 16 + (lane >> 2);
        #pragma unroll
        for (int nt = 0; nt < 8; nt++) {
            int col = h * DH_ + nt * 8 + (lane & 3) * 2;
            *(uint32_t*)(g_att + (size_t)r0g * D_ + col) =
                pack_h2(O[mt][nt][0] * inv0, O[mt][nt][1] * inv0);
            *(uint32_t*)(g_att + (size_t)(r0g + 8) * D_ + col) =
                pack_h2(O[mt][nt][2] * inv1, O[mt][nt][3] * inv1);
        }
    }
}

// ---------------------------------------------------------------------------
// Launch
// ---------------------------------------------------------------------------
extern "C" void kernel_launch(void* const* d_in, const int* in_sizes, int n_in,
                              void* d_out, int out_size)
{
    const float* x    = (const float*)d_in[0];
    const float* Wqkv = (const float*)d_in[1];
    const float* Wout = (const float*)d_in[2];
    float* out = (float*)d_out;

    __half *xh, *wqh, *woh, *qkv, *att;
    cudaGetSymbolAddress((void**)&xh,  g_xh);
    cudaGetSymbolAddress((void**)&wqh, g_wqh);
    cudaGetSymbolAddress((void**)&woh, g_woh);
    cudaGetSymbolAddress((void**)&qkv, g_qkv);
    cudaGetSymbolAddress((void**)&att, g_att);

    cudaFuncSetAttribute((const void*)gemm_mma<true, true>,
                         cudaFuncAttributeMaxDynamicSharedMemorySize, GEMM_SMEM);
    cudaFuncSetAttribute((const void*)gemm_mma<false, false>,
                         cudaFuncAttributeMaxDynamicSharedMemorySize, GEMM_SMEM);
    cudaFuncSetAttribute(attn_mma,
                         cudaFuncAttributeMaxDynamicSharedMemorySize, ATT_SMEM);

    // 0) convert inputs to fp16
    conv_f16<<<512, 256>>>(x,    xh,  M_TOT * D_);
    conv_f16<<<512, 256>>>(Wqkv, wqh, QKV_N * D_);
    conv_f16<<<256, 256>>>(Wout, woh, D_ * D_);

    // 1) qkv = x @ Wqkv^T -> fp16 (q columns pre-scaled by SCALE*log2e)
    gemm_mma<true, true><<<dim3(QKV_N / 256, M_TOT / 128), 256, GEMM_SMEM>>>(
        xh, wqh, nullptr, qkv, QKV_N);

    // 2) attention -> g_att (fp16)
    attn_mma<<<dim3(S_ / 128, B_ * H_), 128, ATT_SMEM>>>();

    // 3) out = attn @ Wout^T -> fp32
    gemm_mma<false, false><<<dim3(D_ / 256, M_TOT / 128), 256, GEMM_SMEM>>>(
        att, woh, out, nullptr, D_);
}

// round 16
// speedup vs baseline: 1.0655x; 1.0273x over previous
#include <cuda_runtime.h>
#include <cuda_fp16.h>
#include <math.h>
#include <stdint.h>

// ---------------------------------------------------------------------------
// Problem constants
// ---------------------------------------------------------------------------
#define B_    2
#define S_    2048
#define D_    1024
#define H_    16
#define DH_   64
#define M_TOT (B_ * S_)      // 4096
#define QKV_N (3 * D_)       // 3072
#define K_    1024
#define SCALE 0.125f
#define LOG2E 1.4426950408889634f

// ---------------------------------------------------------------------------
// Scratch: single fp16 (q pre-scaled by SCALE*log2(e) in GEMM1 epilogue)
// ---------------------------------------------------------------------------
__device__ __half g_xh[M_TOT * D_];
__device__ __half g_wqh[QKV_N * D_];
__device__ __half g_woh[D_ * D_];
__device__ __half g_qkv[M_TOT * QKV_N];
__device__ __half g_att[M_TOT * D_];

// ---------------------------------------------------------------------------
// Helpers
// ---------------------------------------------------------------------------
__device__ __forceinline__ uint32_t sptr(const void* p) {
    return (uint32_t)__cvta_generic_to_shared(p);
}
__device__ __forceinline__ void cp16(uint32_t d, const void* s) {
    asm volatile("cp.async.cg.shared.global [%0], [%1], 16;" :: "r"(d), "l"(s));
}
#define CP_COMMIT() asm volatile("cp.async.commit_group;" ::: "memory")
#define CP_WAIT(n)  asm volatile("cp.async.wait_group %0;" :: "n"(n) : "memory")

__device__ __forceinline__ uint32_t sw128(uint32_t o) {   // Swizzle<3,4,3>
    return o ^ ((o >> 3) & 0x70);
}
__device__ __forceinline__ void ldsm4(uint32_t a, uint32_t r[4]) {
    asm volatile("ldmatrix.sync.aligned.m8n8.x4.shared.b16 {%0,%1,%2,%3}, [%4];"
                 : "=r"(r[0]), "=r"(r[1]), "=r"(r[2]), "=r"(r[3]) : "r"(a));
}
__device__ __forceinline__ void ldsm4t(uint32_t a, uint32_t r[4]) {
    asm volatile("ldmatrix.sync.aligned.m8n8.x4.trans.shared.b16 {%0,%1,%2,%3}, [%4];"
                 : "=r"(r[0]), "=r"(r[1]), "=r"(r[2]), "=r"(r[3]) : "r"(a));
}
__device__ __forceinline__ void mma_f16(float c[4], const uint32_t a[4],
                                        uint32_t b0, uint32_t b1) {
    asm volatile(
        "mma.sync.aligned.m16n8k16.row.col.f32.f16.f16.f32 "
        "{%0,%1,%2,%3}, {%4,%5,%6,%7}, {%8,%9}, {%0,%1,%2,%3};"
        : "+f"(c[0]), "+f"(c[1]), "+f"(c[2]), "+f"(c[3])
        : "r"(a[0]), "r"(a[1]), "r"(a[2]), "r"(a[3]), "r"(b0), "r"(b1));
}
__device__ __forceinline__ uint32_t pack_h2(float a, float b) {
    __half2 hp = __floats2half2_rn(a, b);
    return *(uint32_t*)&hp;
}
__device__ __forceinline__ uint32_t ex2h2(uint32_t x) {
    uint32_t r;
    asm("ex2.approx.f16x2 %0, %1;" : "=r"(r) : "r"(x));
    return r;
}
__device__ __forceinline__ float2 h2f2(uint32_t x) {
    return __half22float2(*(__half2*)&x);
}

// ---------------------------------------------------------------------------
// Fused convert: fp32 -> fp16 for all three inputs in one launch
// ---------------------------------------------------------------------------
__global__ void conv_all(const float* __restrict__ s0, __half* __restrict__ d0, int n0,
                         const float* __restrict__ s1, __half* __restrict__ d1, int n1,
                         const float* __restrict__ s2, __half* __restrict__ d2, int n2)
{
    int tot4 = (n0 + n1 + n2) >> 2;
    int b0 = n0 >> 2, b1 = (n0 + n1) >> 2;
    for (int i4 = blockIdx.x * blockDim.x + threadIdx.x; i4 < tot4;
         i4 += gridDim.x * blockDim.x) {
        const float* src;
        __half* dst;
        int off;
        if (i4 < b0)      { src = s0; dst = d0; off = i4 << 2; }
        else if (i4 < b1) { src = s1; dst = d1; off = (i4 - b0) << 2; }
        else              { src = s2; dst = d2; off = (i4 - b1) << 2; }
        float4 v = *(const float4*)(src + off);
        __half2 a = __floats2half2_rn(v.x, v.y);
        __half2 b = __floats2half2_rn(v.z, v.w);
        uint2 o = { *(uint32_t*)&a, *(uint32_t*)&b };
        *(uint2*)(dst + off) = o;
    }
}

// ---------------------------------------------------------------------------
// GEMM: C[M,N] = A[M,1024] @ B[N,1024]^T, single-pass fp16, f32 accum.
// CTA 128x256, 8 warps (2x4, warp tile 64x64), BK=64, 3-stage cp.async,
// SW128 smem. QSCALE folds SCALE*log2e into q columns.  (R13-proven, 85us)
// ---------------------------------------------------------------------------
#define GA 16384
#define GB 32768
#define GST (GA + GB)                   // 49152
#define GEMM_SMEM (3 * GST)             // 147456
#define NCH 16

template<bool HOUT, bool QSCALE>
__global__ __launch_bounds__(256) void gemm_mma(
    const __half* __restrict__ As, const __half* __restrict__ Bs,
    float* __restrict__ Cf, __half* __restrict__ Ch, int N)
{
    extern __shared__ char smx[];
    const int tid = threadIdx.x, lane = tid & 31, wid = tid >> 5;
    const int bm = blockIdx.y * 128, bn = blockIdx.x * 256;
    const int m0 = (wid >> 2) * 64, n0 = (wid & 3) * 64;

    const __half* pA = As + (size_t)bm * K_;
    const __half* pB = Bs + (size_t)bn * K_;

    float acc[4][8][4];
    #pragma unroll
    for (int i = 0; i < 4; i++)
        #pragma unroll
        for (int j = 0; j < 8; j++)
            #pragma unroll
            for (int q = 0; q < 4; q++) acc[i][j][q] = 0.0f;

    auto load_stage = [&](int s, int k0) {
        char* base = smx + s * GST;
        #pragma unroll
        for (int i = 0; i < 4; i++) {
            int idx = tid + i * 256;
            int r = idx >> 3, c = idx & 7;
            cp16(sptr(base) + sw128((uint32_t)(r * 128 + c * 16)),
                 pA + (size_t)r * K_ + k0 + c * 8);
        }
        #pragma unroll
        for (int i = 0; i < 8; i++) {
            int idx = tid + i * 256;
            int r = idx >> 3, c = idx & 7;
            cp16(sptr(base + GA) + sw128((uint32_t)(r * 128 + c * 16)),
                 pB + (size_t)r * K_ + k0 + c * 8);
        }
    };

    load_stage(0, 0);   CP_COMMIT();
    load_stage(1, 64);  CP_COMMIT();

    const int row_in = lane & 7, g = lane >> 3;

    for (int kc = 0; kc < NCH; kc++) {
        if (kc == NCH - 1) { CP_WAIT(0); } else { CP_WAIT(1); }
        __syncthreads();
        if (kc + 2 < NCH) {
            load_stage((kc + 2) % 3, (kc + 2) * 64);
            CP_COMMIT();
        }

        char* base = smx + (kc % 3) * GST;
        uint32_t bA = sptr(base), bB = bA + GA;

        #pragma unroll
        for (int ks = 0; ks < 4; ks++) {
            uint32_t af[4][4];
            #pragma unroll
            for (int mt = 0; mt < 4; mt++) {
                uint32_t off = sw128((uint32_t)(m0 + mt * 16 + row_in + (g & 1) * 8) * 128
                                     + (ks * 16 + (g >> 1) * 8) * 2);
                ldsm4(bA + off, af[mt]);
            }
            #pragma unroll
            for (int gb = 0; gb < 4; gb++) {
                uint32_t bf[4];
                uint32_t off = sw128((uint32_t)(n0 + gb * 16 + ((g >> 1) & 1) * 8 + row_in) * 128
                                     + (ks * 16 + (g & 1) * 8) * 2);
                ldsm4(bB + off, bf);
                #pragma unroll
                for (int mt = 0; mt < 4; mt++)
                    #pragma unroll
                    for (int hf = 0; hf < 2; hf++) {
                        int nt = gb * 2 + hf, ix = hf * 2;
                        mma_f16(acc[mt][nt], af[mt], bf[ix], bf[ix + 1]);
                    }
            }
        }
    }

    #pragma unroll
    for (int mt = 0; mt < 4; mt++)
        #pragma unroll
        for (int nt = 0; nt < 8; nt++) {
            int row = bm + m0 + mt * 16 + (lane >> 2);
            int col = bn + n0 + nt * 8 + (lane & 3) * 2;
            float* c = acc[mt][nt];
            float sc = (QSCALE && col < D_) ? (SCALE * LOG2E) : 1.0f;
            if (HOUT) {
                *(uint32_t*)(Ch + (size_t)row * N + col) = pack_h2(c[0] * sc, c[1] * sc);
                *(uint32_t*)(Ch + (size_t)(row + 8) * N + col) = pack_h2(c[2] * sc, c[3] * sc);
            } else {
                *(float2*)(Cf + (size_t)row * N + col) = make_float2(c[0], c[1]);
                *(float2*)(Cf + (size_t)(row + 8) * N + col) = make_float2(c[2], c[3]);
            }
        }
}

// ---------------------------------------------------------------------------
// Flash attention: 4 warps x 32 q-rows, single-pass fp16, log2-domain
// softmax (ex2.approx.f16x2). Per-mt softmax->PV interleaving so each mt's
// MUFU stream overlaps the other's HMMA stream. 2-stage KV double-buffer,
// smem 48 KB, 128 threads, 2 CTAs/SM.
// ---------------------------------------------------------------------------
#define SQ   0
#define SKV0 16384
#define KVSTAGE 16384            // K 8192 | V 8192
#define ATT_SMEM (SKV0 + 2 * KVSTAGE)   // 49152
#define NT (S_ / 64)             // 32

__global__ __launch_bounds__(128, 2) void attn_mma()
{
    extern __shared__ char smx[];
    const int tid = threadIdx.x, lane = tid & 31, warp = tid >> 5;
    const int qt = blockIdx.x;
    const int b  = blockIdx.y >> 4;
    const int h  = blockIdx.y & 15;
    const int qrow0 = b * S_ + qt * 128;

    const __half* qp = g_qkv + (size_t)qrow0 * QKV_N + h * DH_;
    const __half* kp = g_qkv + (size_t)(b * S_) * QKV_N + D_ + h * DH_;
    const __half* vp = g_qkv + (size_t)(b * S_) * QKV_N + 2 * D_ + h * DH_;

    uint32_t sb = sptr(smx);

    // Q tile: 128 rows x 128B, SW128
    #pragma unroll
    for (int i = 0; i < 8; i++) {
        int idx = tid + i * 128;
        int r = idx >> 3, c = idx & 7;
        cp16(sb + SQ + sw128((uint32_t)(r * 128 + c * 16)), qp + (size_t)r * QKV_N + c * 8);
    }
    CP_COMMIT();

    auto ld_kv = [&](int s, int krow) {
        uint32_t base = sb + SKV0 + s * KVSTAGE;
        #pragma unroll
        for (int i = 0; i < 4; i++) {
            int idx = tid + i * 128;
            int r = idx >> 3, c = idx & 7;
            size_t go = (size_t)(krow + r) * QKV_N + c * 8;
            uint32_t so = sw128((uint32_t)(r * 128 + c * 16));
            cp16(base + so,        kp + go);
            cp16(base + 8192 + so, vp + go);
        }
    };

    ld_kv(0, 0);
    CP_COMMIT();
    CP_WAIT(1);
    __syncthreads();

    const int row_in = lane & 7, g = lane >> 3;

    uint32_t qa[2][4][4];
    #pragma unroll
    for (int mt = 0; mt < 2; mt++)
        #pragma unroll
        for (int ks = 0; ks < 4; ks++) {
            uint32_t off = sw128((uint32_t)(warp * 32 + mt * 16 + row_in + (g & 1) * 8) * 128
                                 + (ks * 16 + (g >> 1) * 8) * 2);
            ldsm4(sb + SQ + off, qa[mt][ks]);
        }

    float m[4] = {-1e30f, -1e30f, -1e30f, -1e30f};
    float l[4] = {0.0f, 0.0f, 0.0f, 0.0f};
    float O[2][8][4];
    #pragma unroll
    for (int mt = 0; mt < 2; mt++)
        #pragma unroll
        for (int nt = 0; nt < 8; nt++)
            #pragma unroll
            for (int q = 0; q < 4; q++) O[mt][nt][q] = 0.0f;

    for (int kt = 0; kt < NT; kt++) {
        if (kt + 1 < NT) {
            ld_kv((kt + 1) & 1, (kt + 1) * 64);
            CP_COMMIT();
            CP_WAIT(1);
        } else {
            CP_WAIT(0);
        }
        __syncthreads();

        uint32_t kvb = sb + SKV0 + (kt & 1) * KVSTAGE;

        // ---- S = Q @ K^T (log2-domain: SCALE*log2e folded into Q) ----
        float s[2][8][4];
        #pragma unroll
        for (int mt = 0; mt < 2; mt++)
            #pragma unroll
            for (int nt = 0; nt < 8; nt++)
                #pragma unroll
                for (int q = 0; q < 4; q++) s[mt][nt][q] = 0.0f;

        #pragma unroll
        for (int ks = 0; ks < 4; ks++) {
            #pragma unroll
            for (int gb = 0; gb < 4; gb++) {
                uint32_t bf[4];
                uint32_t off = sw128((uint32_t)(gb * 16 + ((g >> 1) & 1) * 8 + row_in) * 128
                                     + (ks * 16 + (g & 1) * 8) * 2);
                ldsm4(kvb + off, bf);
                #pragma unroll
                for (int mt = 0; mt < 2; mt++)
                    #pragma unroll
                    for (int hf = 0; hf < 2; hf++) {
                        int nt = gb * 2 + hf, ix = hf * 2;
                        mma_f16(s[mt][nt], qa[mt][ks], bf[ix], bf[ix + 1]);
                    }
            }
        }

        // ---- per-mt: softmax (ex2.f16x2) then PV immediately ----
        #pragma unroll
        for (int mt = 0; mt < 2; mt++) {
            float mx0 = -1e30f, mx1 = -1e30f;
            #pragma unroll
            for (int nt = 0; nt < 8; nt++) {
                mx0 = fmaxf(mx0, fmaxf(s[mt][nt][0], s[mt][nt][1]));
                mx1 = fmaxf(mx1, fmaxf(s[mt][nt][2], s[mt][nt][3]));
            }
            mx0 = fmaxf(mx0, __shfl_xor_sync(0xffffffffu, mx0, 1));
            mx0 = fmaxf(mx0, __shfl_xor_sync(0xffffffffu, mx0, 2));
            mx1 = fmaxf(mx1, __shfl_xor_sync(0xffffffffu, mx1, 1));
            mx1 = fmaxf(mx1, __shfl_xor_sync(0xffffffffu, mx1, 2));

            float mn0 = fmaxf(m[2 * mt], mx0), mn1 = fmaxf(m[2 * mt + 1], mx1);
            if (mn0 > m[2 * mt] || mn1 > m[2 * mt + 1]) {
                float c0 = exp2f(m[2 * mt] - mn0), c1 = exp2f(m[2 * mt + 1] - mn1);
                l[2 * mt] *= c0; l[2 * mt + 1] *= c1;
                #pragma unroll
                for (int nt = 0; nt < 8; nt++) {
                    O[mt][nt][0] *= c0; O[mt][nt][1] *= c0;
                    O[mt][nt][2] *= c1; O[mt][nt][3] *= c1;
                }
                m[2 * mt] = mn0; m[2 * mt + 1] = mn1;
            }
            float m0v = m[2 * mt], m1v = m[2 * mt + 1];
            float sum0 = 0.0f, sum1 = 0.0f;
            uint32_t ph[8][2];
            #pragma unroll
            for (int nt = 0; nt < 8; nt++) {
                uint32_t p01 = ex2h2(pack_h2(s[mt][nt][0] - m0v, s[mt][nt][1] - m0v));
                uint32_t p23 = ex2h2(pack_h2(s[mt][nt][2] - m1v, s[mt][nt][3] - m1v));
                ph[nt][0] = p01;
                ph[nt][1] = p23;
                float2 f0 = h2f2(p01);
                float2 f1 = h2f2(p23);
                sum0 += f0.x + f0.y;
                sum1 += f1.x + f1.y;
            }
            sum0 += __shfl_xor_sync(0xffffffffu, sum0, 1);
            sum0 += __shfl_xor_sync(0xffffffffu, sum0, 2);
            sum1 += __shfl_xor_sync(0xffffffffu, sum1, 1);
            sum1 += __shfl_xor_sync(0xffffffffu, sum1, 2);
            l[2 * mt] += sum0;
            l[2 * mt + 1] += sum1;

            // PV for this mt (overlaps next mt's softmax MUFU stream)
            #pragma unroll
            for (int j = 0; j < 4; j++) {
                uint32_t pa[4] = { ph[2 * j][0], ph[2 * j][1],
                                   ph[2 * j + 1][0], ph[2 * j + 1][1] };
                #pragma unroll
                for (int gv = 0; gv < 4; gv++) {
                    uint32_t vf[4];
                    uint32_t off = sw128((uint32_t)(j * 16 + (g & 1) * 8 + row_in) * 128
                                         + (gv * 16 + (g >> 1) * 8) * 2);
                    ldsm4t(kvb + 8192 + off, vf);
                    #pragma unroll
                    for (int hf = 0; hf < 2; hf++) {
                        int nt = gv * 2 + hf, ix = hf * 2;
                        mma_f16(O[mt][nt], pa, vf[ix], vf[ix + 1]);
                    }
                }
            }
        }
        __syncthreads();
    }

    // ---- epilogue: normalize, write fp16 ----
    #pragma unroll
    for (int mt = 0; mt < 2; mt++) {
        float inv0 = 1.0f / (l[2 * mt] + 1e-6f);
        float inv1 = 1.0f / (l[2 * mt + 1] + 1e-6f);
        int r0g = qrow0 + warp * 32 + mt * 16 + (lane >> 2);
        #pragma unroll
        for (int nt = 0; nt < 8; nt++) {
            int col = h * DH_ + nt * 8 + (lane & 3) * 2;
            *(uint32_t*)(g_att + (size_t)r0g * D_ + col) =
                pack_h2(O[mt][nt][0] * inv0, O[mt][nt][1] * inv0);
            *(uint32_t*)(g_att + (size_t)(r0g + 8) * D_ + col) =
                pack_h2(O[mt][nt][2] * inv1, O[mt][nt][3] * inv1);
        }
    }
}

// ---------------------------------------------------------------------------
// Launch
// ---------------------------------------------------------------------------
extern "C" void kernel_launch(void* const* d_in, const int* in_sizes, int n_in,
                              void* d_out, int out_size)
{
    const float* x    = (const float*)d_in[0];
    const float* Wqkv = (const float*)d_in[1];
    const float* Wout = (const float*)d_in[2];
    float* out = (float*)d_out;

    __half *xh, *wqh, *woh, *qkv, *att;
    cudaGetSymbolAddress((void**)&xh,  g_xh);
    cudaGetSymbolAddress((void**)&wqh, g_wqh);
    cudaGetSymbolAddress((void**)&woh, g_woh);
    cudaGetSymbolAddress((void**)&qkv, g_qkv);
    cudaGetSymbolAddress((void**)&att, g_att);

    cudaFuncSetAttribute((const void*)gemm_mma<true, true>,
                         cudaFuncAttributeMaxDynamicSharedMemorySize, GEMM_SMEM);
    cudaFuncSetAttribute((const void*)gemm_mma<false, false>,
                         cudaFuncAttributeMaxDynamicSharedMemorySize, GEMM_SMEM);
    cudaFuncSetAttribute(attn_mma,
                         cudaFuncAttributeMaxDynamicSharedMemorySize, ATT_SMEM);

    // 0) convert all inputs to fp16 in one launch
    conv_all<<<592, 256>>>(x,    xh,  M_TOT * D_,
                           Wqkv, wqh, QKV_N * D_,
                           Wout, woh, D_ * D_);

    // 1) qkv = x @ Wqkv^T -> fp16 (q columns pre-scaled by SCALE*log2e)
    gemm_mma<true, true><<<dim3(QKV_N / 256, M_TOT / 128), 256, GEMM_SMEM>>>(
        xh, wqh, nullptr, qkv, QKV_N);

    // 2) attention -> g_att (fp16)
    attn_mma<<<dim3(S_ / 128, B_ * H_), 128, ATT_SMEM>>>();

    // 3) out = attn @ Wout^T -> fp32
    gemm_mma<false, false><<<dim3(D_ / 256, M_TOT / 128), 256, GEMM_SMEM>>>(
        att, woh, out, nullptr, D_);
}

// round 17
// speedup vs baseline: 1.1343x; 1.0645x over previous
#include <cuda_runtime.h>
#include <cuda_fp16.h>
#include <math.h>
#include <stdint.h>

// ---------------------------------------------------------------------------
// Problem constants
// ---------------------------------------------------------------------------
#define B_    2
#define S_    2048
#define D_    1024
#define H_    16
#define DH_   64
#define M_TOT (B_ * S_)      // 4096
#define QKV_N (3 * D_)       // 3072
#define K_    1024
#define SCALE 0.125f
#define LOG2E 1.4426950408889634f

// ---------------------------------------------------------------------------
// Scratch: single fp16 (q pre-scaled by SCALE*log2(e) in GEMM1 epilogue)
// ---------------------------------------------------------------------------
__device__ __half g_xh[M_TOT * D_];
__device__ __half g_wqh[QKV_N * D_];
__device__ __half g_woh[D_ * D_];
__device__ __half g_qkv[M_TOT * QKV_N];
__device__ __half g_att[M_TOT * D_];

// ---------------------------------------------------------------------------
// Helpers
// ---------------------------------------------------------------------------
__device__ __forceinline__ uint32_t sptr(const void* p) {
    return (uint32_t)__cvta_generic_to_shared(p);
}
__device__ __forceinline__ void cp16(uint32_t d, const void* s) {
    asm volatile("cp.async.cg.shared.global [%0], [%1], 16;" :: "r"(d), "l"(s));
}
#define CP_COMMIT() asm volatile("cp.async.commit_group;" ::: "memory")
#define CP_WAIT(n)  asm volatile("cp.async.wait_group %0;" :: "n"(n) : "memory")

__device__ __forceinline__ uint32_t sw128(uint32_t o) {   // Swizzle<3,4,3>
    return o ^ ((o >> 3) & 0x70);
}
__device__ __forceinline__ void ldsm4(uint32_t a, uint32_t r[4]) {
    asm volatile("ldmatrix.sync.aligned.m8n8.x4.shared.b16 {%0,%1,%2,%3}, [%4];"
                 : "=r"(r[0]), "=r"(r[1]), "=r"(r[2]), "=r"(r[3]) : "r"(a));
}
__device__ __forceinline__ void ldsm4t(uint32_t a, uint32_t r[4]) {
    asm volatile("ldmatrix.sync.aligned.m8n8.x4.trans.shared.b16 {%0,%1,%2,%3}, [%4];"
                 : "=r"(r[0]), "=r"(r[1]), "=r"(r[2]), "=r"(r[3]) : "r"(a));
}
__device__ __forceinline__ void mma_f16(float c[4], const uint32_t a[4],
                                        uint32_t b0, uint32_t b1) {
    asm volatile(
        "mma.sync.aligned.m16n8k16.row.col.f32.f16.f16.f32 "
        "{%0,%1,%2,%3}, {%4,%5,%6,%7}, {%8,%9}, {%0,%1,%2,%3};"
        : "+f"(c[0]), "+f"(c[1]), "+f"(c[2]), "+f"(c[3])
        : "r"(a[0]), "r"(a[1]), "r"(a[2]), "r"(a[3]), "r"(b0), "r"(b1));
}
__device__ __forceinline__ uint32_t pack_h2(float a, float b) {
    __half2 hp = __floats2half2_rn(a, b);
    return *(uint32_t*)&hp;
}
__device__ __forceinline__ uint32_t ex2h2(uint32_t x) {
    uint32_t r;
    asm("ex2.approx.f16x2 %0, %1;" : "=r"(r) : "r"(x));
    return r;
}
__device__ __forceinline__ float2 h2f2(uint32_t x) {
    return __half22float2(*(__half2*)&x);
}

// ---------------------------------------------------------------------------
// Fused convert: fp32 -> fp16 for all three inputs in one launch
// ---------------------------------------------------------------------------
__global__ void conv_all(const float* __restrict__ s0, __half* __restrict__ d0, int n0,
                         const float* __restrict__ s1, __half* __restrict__ d1, int n1,
                         const float* __restrict__ s2, __half* __restrict__ d2, int n2)
{
    int tot4 = (n0 + n1 + n2) >> 2;
    int b0 = n0 >> 2, b1 = (n0 + n1) >> 2;
    for (int i4 = blockIdx.x * blockDim.x + threadIdx.x; i4 < tot4;
         i4 += gridDim.x * blockDim.x) {
        const float* src;
        __half* dst;
        int off;
        if (i4 < b0)      { src = s0; dst = d0; off = i4 << 2; }
        else if (i4 < b1) { src = s1; dst = d1; off = (i4 - b0) << 2; }
        else              { src = s2; dst = d2; off = (i4 - b1) << 2; }
        float4 v = *(const float4*)(src + off);
        __half2 a = __floats2half2_rn(v.x, v.y);
        __half2 b = __floats2half2_rn(v.z, v.w);
        uint2 o = { *(uint32_t*)&a, *(uint32_t*)&b };
        *(uint2*)(dst + off) = o;
    }
}

// ---------------------------------------------------------------------------
// GEMM: C[M,N] = A[M,1024] @ B[N,1024]^T, single-pass fp16, f32 accum.
// CTA 128x128, 4 warps (2x2 grid, warp tile 64x64), BK=64 (128 mma/warp per
// barrier), 3-stage cp.async, SW128 smem (32 KB/stage), 2 CTAs/SM.
// ---------------------------------------------------------------------------
#define GA 16384                        // A tile bytes (128 x 128B)
#define GB 16384                        // B tile bytes (128 x 128B)
#define GST (GA + GB)                   // 32768
#define GEMM_SMEM (3 * GST)             // 98304
#define NCH 16

template<bool HOUT, bool QSCALE>
__global__ __launch_bounds__(128, 2) void gemm_mma(
    const __half* __restrict__ As, const __half* __restrict__ Bs,
    float* __restrict__ Cf, __half* __restrict__ Ch, int N)
{
    extern __shared__ char smx[];
    const int tid = threadIdx.x, lane = tid & 31, wid = tid >> 5;   // 4 warps
    const int bm = blockIdx.y * 128, bn = blockIdx.x * 128;
    const int m0 = (wid >> 1) * 64, n0 = (wid & 1) * 64;

    const __half* pA = As + (size_t)bm * K_;
    const __half* pB = Bs + (size_t)bn * K_;

    float acc[4][8][4];
    #pragma unroll
    for (int i = 0; i < 4; i++)
        #pragma unroll
        for (int j = 0; j < 8; j++)
            #pragma unroll
            for (int q = 0; q < 4; q++) acc[i][j][q] = 0.0f;

    auto load_stage = [&](int s, int k0) {
        char* base = smx + s * GST;
        #pragma unroll
        for (int i = 0; i < 8; i++) {       // A: 128 rows x 8 x 16B
            int idx = tid + i * 128;
            int r = idx >> 3, c = idx & 7;
            cp16(sptr(base) + sw128((uint32_t)(r * 128 + c * 16)),
                 pA + (size_t)r * K_ + k0 + c * 8);
        }
        #pragma unroll
        for (int i = 0; i < 8; i++) {       // B: 128 rows x 8 x 16B
            int idx = tid + i * 128;
            int r = idx >> 3, c = idx & 7;
            cp16(sptr(base + GA) + sw128((uint32_t)(r * 128 + c * 16)),
                 pB + (size_t)r * K_ + k0 + c * 8);
        }
    };

    load_stage(0, 0);   CP_COMMIT();
    load_stage(1, 64);  CP_COMMIT();

    const int row_in = lane & 7, g = lane >> 3;

    for (int kc = 0; kc < NCH; kc++) {
        if (kc == NCH - 1) { CP_WAIT(0); } else { CP_WAIT(1); }
        __syncthreads();
        if (kc + 2 < NCH) {
            load_stage((kc + 2) % 3, (kc + 2) * 64);
            CP_COMMIT();
        }

        char* base = smx + (kc % 3) * GST;
        uint32_t bA = sptr(base), bB = bA + GA;

        #pragma unroll
        for (int ks = 0; ks < 4; ks++) {
            uint32_t af[4][4];
            #pragma unroll
            for (int mt = 0; mt < 4; mt++) {
                uint32_t off = sw128((uint32_t)(m0 + mt * 16 + row_in + (g & 1) * 8) * 128
                                     + (ks * 16 + (g >> 1) * 8) * 2);
                ldsm4(bA + off, af[mt]);
            }
            #pragma unroll
            for (int gb = 0; gb < 4; gb++) {
                uint32_t bf[4];
                uint32_t off = sw128((uint32_t)(n0 + gb * 16 + ((g >> 1) & 1) * 8 + row_in) * 128
                                     + (ks * 16 + (g & 1) * 8) * 2);
                ldsm4(bB + off, bf);
                #pragma unroll
                for (int mt = 0; mt < 4; mt++)
                    #pragma unroll
                    for (int hf = 0; hf < 2; hf++) {
                        int nt = gb * 2 + hf, ix = hf * 2;
                        mma_f16(acc[mt][nt], af[mt], bf[ix], bf[ix + 1]);
                    }
            }
        }
    }

    #pragma unroll
    for (int mt = 0; mt < 4; mt++)
        #pragma unroll
        for (int nt = 0; nt < 8; nt++) {
            int row = bm + m0 + mt * 16 + (lane >> 2);
            int col = bn + n0 + nt * 8 + (lane & 3) * 2;
            float* c = acc[mt][nt];
            float sc = (QSCALE && col < D_) ? (SCALE * LOG2E) : 1.0f;
            if (HOUT) {
                *(uint32_t*)(Ch + (size_t)row * N + col) = pack_h2(c[0] * sc, c[1] * sc);
                *(uint32_t*)(Ch + (size_t)(row + 8) * N + col) = pack_h2(c[2] * sc, c[3] * sc);
            } else {
                *(float2*)(Cf + (size_t)row * N + col) = make_float2(c[0], c[1]);
                *(float2*)(Cf + (size_t)(row + 8) * N + col) = make_float2(c[2], c[3]);
            }
        }
}

// ---------------------------------------------------------------------------
// Flash attention: 4 warps x 32 q-rows, single-pass fp16, log2-domain
// softmax (ex2.approx.f16x2), per-mt softmax->PV interleaving. 2-stage KV
// double-buffer, smem 48 KB, 128 threads, 2 CTAs/SM.  (R16-proven)
// ---------------------------------------------------------------------------
#define SQ   0
#define SKV0 16384
#define KVSTAGE 16384
#define ATT_SMEM (SKV0 + 2 * KVSTAGE)   // 49152
#define NT (S_ / 64)

__global__ __launch_bounds__(128, 2) void attn_mma()
{
    extern __shared__ char smx[];
    const int tid = threadIdx.x, lane = tid & 31, warp = tid >> 5;
    const int qt = blockIdx.x;
    const int b  = blockIdx.y >> 4;
    const int h  = blockIdx.y & 15;
    const int qrow0 = b * S_ + qt * 128;

    const __half* qp = g_qkv + (size_t)qrow0 * QKV_N + h * DH_;
    const __half* kp = g_qkv + (size_t)(b * S_) * QKV_N + D_ + h * DH_;
    const __half* vp = g_qkv + (size_t)(b * S_) * QKV_N + 2 * D_ + h * DH_;

    uint32_t sb = sptr(smx);

    #pragma unroll
    for (int i = 0; i < 8; i++) {
        int idx = tid + i * 128;
        int r = idx >> 3, c = idx & 7;
        cp16(sb + SQ + sw128((uint32_t)(r * 128 + c * 16)), qp + (size_t)r * QKV_N + c * 8);
    }
    CP_COMMIT();

    auto ld_kv = [&](int s, int krow) {
        uint32_t base = sb + SKV0 + s * KVSTAGE;
        #pragma unroll
        for (int i = 0; i < 4; i++) {
            int idx = tid + i * 128;
            int r = idx >> 3, c = idx & 7;
            size_t go = (size_t)(krow + r) * QKV_N + c * 8;
            uint32_t so = sw128((uint32_t)(r * 128 + c * 16));
            cp16(base + so,        kp + go);
            cp16(base + 8192 + so, vp + go);
        }
    };

    ld_kv(0, 0);
    CP_COMMIT();
    CP_WAIT(1);
    __syncthreads();

    const int row_in = lane & 7, g = lane >> 3;

    uint32_t qa[2][4][4];
    #pragma unroll
    for (int mt = 0; mt < 2; mt++)
        #pragma unroll
        for (int ks = 0; ks < 4; ks++) {
            uint32_t off = sw128((uint32_t)(warp * 32 + mt * 16 + row_in + (g & 1) * 8) * 128
                                 + (ks * 16 + (g >> 1) * 8) * 2);
            ldsm4(sb + SQ + off, qa[mt][ks]);
        }

    float m[4] = {-1e30f, -1e30f, -1e30f, -1e30f};
    float l[4] = {0.0f, 0.0f, 0.0f, 0.0f};
    float O[2][8][4];
    #pragma unroll
    for (int mt = 0; mt < 2; mt++)
        #pragma unroll
        for (int nt = 0; nt < 8; nt++)
            #pragma unroll
            for (int q = 0; q < 4; q++) O[mt][nt][q] = 0.0f;

    for (int kt = 0; kt < NT; kt++) {
        if (kt + 1 < NT) {
            ld_kv((kt + 1) & 1, (kt + 1) * 64);
            CP_COMMIT();
            CP_WAIT(1);
        } else {
            CP_WAIT(0);
        }
        __syncthreads();

        uint32_t kvb = sb + SKV0 + (kt & 1) * KVSTAGE;

        float s[2][8][4];
        #pragma unroll
        for (int mt = 0; mt < 2; mt++)
            #pragma unroll
            for (int nt = 0; nt < 8; nt++)
                #pragma unroll
                for (int q = 0; q < 4; q++) s[mt][nt][q] = 0.0f;

        #pragma unroll
        for (int ks = 0; ks < 4; ks++) {
            #pragma unroll
            for (int gb = 0; gb < 4; gb++) {
                uint32_t bf[4];
                uint32_t off = sw128((uint32_t)(gb * 16 + ((g >> 1) & 1) * 8 + row_in) * 128
                                     + (ks * 16 + (g & 1) * 8) * 2);
                ldsm4(kvb + off, bf);
                #pragma unroll
                for (int mt = 0; mt < 2; mt++)
                    #pragma unroll
                    for (int hf = 0; hf < 2; hf++) {
                        int nt = gb * 2 + hf, ix = hf * 2;
                        mma_f16(s[mt][nt], qa[mt][ks], bf[ix], bf[ix + 1]);
                    }
            }
        }

        #pragma unroll
        for (int mt = 0; mt < 2; mt++) {
            float mx0 = -1e30f, mx1 = -1e30f;
            #pragma unroll
            for (int nt = 0; nt < 8; nt++) {
                mx0 = fmaxf(mx0, fmaxf(s[mt][nt][0], s[mt][nt][1]));
                mx1 = fmaxf(mx1, fmaxf(s[mt][nt][2], s[mt][nt][3]));
            }
            mx0 = fmaxf(mx0, __shfl_xor_sync(0xffffffffu, mx0, 1));
            mx0 = fmaxf(mx0, __shfl_xor_sync(0xffffffffu, mx0, 2));
            mx1 = fmaxf(mx1, __shfl_xor_sync(0xffffffffu, mx1, 1));
            mx1 = fmaxf(mx1, __shfl_xor_sync(0xffffffffu, mx1, 2));

            float mn0 = fmaxf(m[2 * mt], mx0), mn1 = fmaxf(m[2 * mt + 1], mx1);
            if (mn0 > m[2 * mt] || mn1 > m[2 * mt + 1]) {
                float c0 = exp2f(m[2 * mt] - mn0), c1 = exp2f(m[2 * mt + 1] - mn1);
                l[2 * mt] *= c0; l[2 * mt + 1] *= c1;
                #pragma unroll
                for (int nt = 0; nt < 8; nt++) {
                    O[mt][nt][0] *= c0; O[mt][nt][1] *= c0;
                    O[mt][nt][2] *= c1; O[mt][nt][3] *= c1;
                }
                m[2 * mt] = mn0; m[2 * mt + 1] = mn1;
            }
            float m0v = m[2 * mt], m1v = m[2 * mt + 1];
            float sum0 = 0.0f, sum1 = 0.0f;
            uint32_t ph[8][2];
            #pragma unroll
            for (int nt = 0; nt < 8; nt++) {
                uint32_t p01 = ex2h2(pack_h2(s[mt][nt][0] - m0v, s[mt][nt][1] - m0v));
                uint32_t p23 = ex2h2(pack_h2(s[mt][nt][2] - m1v, s[mt][nt][3] - m1v));
                ph[nt][0] = p01;
                ph[nt][1] = p23;
                float2 f0 = h2f2(p01);
                float2 f1 = h2f2(p23);
                sum0 += f0.x + f0.y;
                sum1 += f1.x + f1.y;
            }
            sum0 += __shfl_xor_sync(0xffffffffu, sum0, 1);
            sum0 += __shfl_xor_sync(0xffffffffu, sum0, 2);
            sum1 += __shfl_xor_sync(0xffffffffu, sum1, 1);
            sum1 += __shfl_xor_sync(0xffffffffu, sum1, 2);
            l[2 * mt] += sum0;
            l[2 * mt + 1] += sum1;

            #pragma unroll
            for (int j = 0; j < 4; j++) {
                uint32_t pa[4] = { ph[2 * j][0], ph[2 * j][1],
                                   ph[2 * j + 1][0], ph[2 * j + 1][1] };
                #pragma unroll
                for (int gv = 0; gv < 4; gv++) {
                    uint32_t vf[4];
                    uint32_t off = sw128((uint32_t)(j * 16 + (g & 1) * 8 + row_in) * 128
                                         + (gv * 16 + (g >> 1) * 8) * 2);
                    ldsm4t(kvb + 8192 + off, vf);
                    #pragma unroll
                    for (int hf = 0; hf < 2; hf++) {
                        int nt = gv * 2 + hf, ix = hf * 2;
                        mma_f16(O[mt][nt], pa, vf[ix], vf[ix + 1]);
                    }
                }
            }
        }
        __syncthreads();
    }

    #pragma unroll
    for (int mt = 0; mt < 2; mt++) {
        float inv0 = 1.0f / (l[2 * mt] + 1e-6f);
        float inv1 = 1.0f / (l[2 * mt + 1] + 1e-6f);
        int r0g = qrow0 + warp * 32 + mt * 16 + (lane >> 2);
        #pragma unroll
        for (int nt = 0; nt < 8; nt++) {
            int col = h * DH_ + nt * 8 + (lane & 3) * 2;
            *(uint32_t*)(g_att + (size_t)r0g * D_ + col) =
                pack_h2(O[mt][nt][0] * inv0, O[mt][nt][1] * inv0);
            *(uint32_t*)(g_att + (size_t)(r0g + 8) * D_ + col) =
                pack_h2(O[mt][nt][2] * inv1, O[mt][nt][3] * inv1);
        }
    }
}

// ---------------------------------------------------------------------------
// Launch
// ---------------------------------------------------------------------------
extern "C" void kernel_launch(void* const* d_in, const int* in_sizes, int n_in,
                              void* d_out, int out_size)
{
    const float* x    = (const float*)d_in[0];
    const float* Wqkv = (const float*)d_in[1];
    const float* Wout = (const float*)d_in[2];
    float* out = (float*)d_out;

    __half *xh, *wqh, *woh, *qkv, *att;
    cudaGetSymbolAddress((void**)&xh,  g_xh);
    cudaGetSymbolAddress((void**)&wqh, g_wqh);
    cudaGetSymbolAddress((void**)&woh, g_woh);
    cudaGetSymbolAddress((void**)&qkv, g_qkv);
    cudaGetSymbolAddress((void**)&att, g_att);

    cudaFuncSetAttribute((const void*)gemm_mma<true, true>,
                         cudaFuncAttributeMaxDynamicSharedMemorySize, GEMM_SMEM);
    cudaFuncSetAttribute((const void*)gemm_mma<false, false>,
                         cudaFuncAttributeMaxDynamicSharedMemorySize, GEMM_SMEM);
    cudaFuncSetAttribute(attn_mma,
                         cudaFuncAttributeMaxDynamicSharedMemorySize, ATT_SMEM);

    // 0) convert all inputs to fp16 in one launch
    conv_all<<<592, 256>>>(x,    xh,  M_TOT * D_,
                           Wqkv, wqh, QKV_N * D_,
                           Wout, woh, D_ * D_);

    // 1) qkv = x @ Wqkv^T -> fp16 (q columns pre-scaled by SCALE*log2e)
    gemm_mma<true, true><<<dim3(QKV_N / 128, M_TOT / 128), 128, GEMM_SMEM>>>(
        xh, wqh, nullptr, qkv, QKV_N);

    // 2) attention -> g_att (fp16)
    attn_mma<<<dim3(S_ / 128, B_ * H_), 128, ATT_SMEM>>>();

    // 3) out = attn @ Wout^T -> fp32
    gemm_mma<false, false><<<dim3(D_ / 128, M_TOT / 128), 128, GEMM_SMEM>>>(
        att, woh, out, nullptr, D_);
}